// round 11
// baseline (speedup 1.0000x reference)
#include <cuda_runtime.h>

// Transitive closure of {0} under (left,right) == reference's 8192-step fixed
// point. One-CTA BFS-until-converged, atomic-free, tuned for ISSUE SLOTS:
// R10 was issue-bound on the polling body (~25 instr/thread/sweep). Now:
//   - done64 kept as 0x01-byte mask -> steady-state sweep is
//     LDS.64 + LOP3 + ISETP + branch (~5 instr); extraction runs only on the
//     few sweeps where a thread actually has new pending bytes
//   - __syncthreads_or for convergence: no flag array, no reset, 1 instr/round
//   - threads with all 8 nodes expanded skip polling entirely
//   - byte-per-node smem map; "set reachable" is a plain STS of constant 1
//   - children in registers (int4); owner-side change detection

#define NNODES    8192
#define NTHREADS  1024
#define SWEEPS    4
#define DONE_ALL  0x0101010101010101ull

__global__ __launch_bounds__(NTHREADS, 1)
void DAGGenome_reach_kernel(const int* __restrict__ left,
                            const int* __restrict__ right,
                            float* __restrict__ out)
{
    __shared__ __align__(16) unsigned char reach8[NNODES];

    const int tid = threadIdx.x;

    // children of my 8 consecutive nodes (coalesced int4 loads, start early)
    const int4* lp = (const int4*)left  + tid * 2;
    const int4* rp = (const int4*)right + tid * 2;
    const int4 l0 = lp[0], l1 = lp[1];
    const int4 r0 = rp[0], r1 = rp[1];
    const int cl[8] = { l0.x, l0.y, l0.z, l0.w, l1.x, l1.y, l1.z, l1.w };
    const int cr[8] = { r0.x, r0.y, r0.z, r0.w, r1.x, r1.y, r1.z, r1.w };

    // init byte map (one u64 store per thread), seed node 0
    ((unsigned long long*)reach8)[tid] = 0ull;
    if (tid == 0) reach8[0] = 1;   // same thread zeroed this word: ordered

    volatile unsigned long long* vmy =
        (volatile unsigned long long*)reach8 + tid;     // my 8 bytes
    volatile unsigned char* vr = (volatile unsigned char*)reach8;

    unsigned long long done64 = 0;   // 0x01 byte per already-expanded node
    __syncthreads();

    // --- BFS to fixed point: one BAR.RED per round ---
    for (;;) {
        int lc_flag = 0;

        if (done64 != DONE_ALL) {
            #pragma unroll 1
            for (int s = 0; s < SWEEPS; s++) {
                const unsigned long long pending = (*vmy) & ~done64;
                if (pending) {
                    lc_flag = 1;
                    done64 |= pending;
                    #pragma unroll
                    for (int j = 0; j < 8; j++) {
                        if (pending & (1ull << (8 * j))) {
                            const int a = cl[j];
                            if (a >= 0) vr[a] = 1;     // plain STS, race-free
                            const int b = cr[j];
                            if (b >= 0) vr[b] = 1;
                        }
                    }
                }
            }
        }

        if (!__syncthreads_or(lc_flag)) break;
    }

    // --- float32 output: my 8 bytes -> 2x float4 stores ---
    const unsigned long long v = *vmy;
    float4 o0, o1;
    o0.x = (v & 0x01ull)      ? 1.0f : 0.0f;
    o0.y = (v & (1ull << 8))  ? 1.0f : 0.0f;
    o0.z = (v & (1ull << 16)) ? 1.0f : 0.0f;
    o0.w = (v & (1ull << 24)) ? 1.0f : 0.0f;
    o1.x = (v & (1ull << 32)) ? 1.0f : 0.0f;
    o1.y = (v & (1ull << 40)) ? 1.0f : 0.0f;
    o1.z = (v & (1ull << 48)) ? 1.0f : 0.0f;
    o1.w = (v & (1ull << 56)) ? 1.0f : 0.0f;
    float4* op = (float4*)out + tid * 2;
    op[0] = o0;
    op[1] = o1;
}

extern "C" void kernel_launch(void* const* d_in, const int* in_sizes, int n_in,
                              void* d_out, int out_size)
{
    const int* left  = (const int*)d_in[1];
    const int* right = (const int*)d_in[2];
    float* out = (float*)d_out;

    DAGGenome_reach_kernel<<<1, NTHREADS>>>(left, right, out);
}